// round 14
// baseline (speedup 1.0000x reference)
#include <cuda_runtime.h>
#include <math.h>

#define NB 4
#define NCOIL 15
#define HH 320
#define WW 320
#define NF 32
#define KS 11
#define HP 342          // 320 + 2*11
#define NLUT 2048
#define LUT_MIN (-1.6f)
#define LUT_SPAN (3.2f)
#define LUT_SCALE ((float)(NLUT - 1) / LUT_SPAN)

// -------- scratch (device globals; no runtime allocation allowed) ----------
__device__ float2 g_upad[NB * HP * HP];            // ~3.7 MB
__device__ float  g_fuk[NB * NF * HP * HP];        // ~60 MB
__device__ float2 g_work[NB * NCOIL * HH * WW];    // ~49 MB
__device__ float2 g_adj[4 * NB * HH * WW];         // 13.1 MB adjoint partials
__device__ float  g_lut[NF * NLUT];
__device__ float2 g_tw[320];                       // W320^j = e^{-2pi i j/320}

// ---------------------------------------------------------------------------
__device__ __forceinline__ float2 cmulf(float2 a, float2 b) {
    return make_float2(fmaf(a.x, b.x, -(a.y * b.y)), fmaf(a.x, b.y, a.y * b.x));
}

// ---- packed f32x2 helpers ----
__device__ __forceinline__ unsigned long long pack2(float x, float y) {
    unsigned long long r;
    asm("mov.b64 %0, {%1,%2};" : "=l"(r) : "f"(x), "f"(y));
    return r;
}
__device__ __forceinline__ void unpack2(unsigned long long v, float& x, float& y) {
    asm("mov.b64 {%0,%1}, %2;" : "=f"(x), "=f"(y) : "l"(v));
}
__device__ __forceinline__ void fma2(unsigned long long& acc,
                                     unsigned long long a, unsigned long long b) {
    asm("fma.rn.f32x2 %0, %1, %2, %0;" : "+l"(acc) : "l"(a), "l"(b));
}

template <int SIGN>
__device__ __forceinline__ float2 twd(const float2* tw, int idx) {
    float2 t = tw[idx];
    return make_float2(t.x, (SIGN < 0) ? t.y : -t.y);
}

// One radix-4 Stockham stage: total length 320 = n*s, n divisible by 4.
template <int SIGN, int n, int s>
__device__ __forceinline__ void stage4(const float2* __restrict__ src,
                                       float2* __restrict__ dst,
                                       const float2* tw, int t) {
    const int m = n / 4;
    const int stride = 320 / n;
    int p = t % m, q = t / m;        // m*s == 80 for all stages used
    float2 a0 = src[q + s * (p + 0 * m)];
    float2 a1 = src[q + s * (p + 1 * m)];
    float2 a2 = src[q + s * (p + 2 * m)];
    float2 a3 = src[q + s * (p + 3 * m)];
    float2 t0 = make_float2(a0.x + a2.x, a0.y + a2.y);
    float2 t1 = make_float2(a0.x - a2.x, a0.y - a2.y);
    float2 t2 = make_float2(a1.x + a3.x, a1.y + a3.y);
    float2 t3 = make_float2(a1.x - a3.x, a1.y - a3.y);
    float2 it3 = make_float2(-t3.y, t3.x);          // i * t3
    float2 A0 = make_float2(t0.x + t2.x, t0.y + t2.y);
    float2 A2 = make_float2(t0.x - t2.x, t0.y - t2.y);
    float2 A1 = make_float2(t1.x + SIGN * it3.x, t1.y + SIGN * it3.y);
    float2 A3 = make_float2(t1.x - SIGN * it3.x, t1.y - SIGN * it3.y);
    dst[q + s * (4 * p + 0)] = A0;
    dst[q + s * (4 * p + 1)] = cmulf(A1, twd<SIGN>(tw, p * stride));
    dst[q + s * (4 * p + 2)] = cmulf(A2, twd<SIGN>(tw, 2 * p * stride));
    dst[q + s * (4 * p + 3)] = cmulf(A3, twd<SIGN>(tw, 3 * p * stride));
}

// 320-point Stockham FFT (radices 5,4,4,4). X,Y: smem buffers (len 320).
template <int SIGN>
__device__ void fft320(float2* X, float2* Y, const float2* tw, int t) {
    if (t < 64) {
        int p = t;
        float2 a[5];
#pragma unroll
        for (int j = 0; j < 5; j++) a[j] = X[p + 64 * j];
#pragma unroll
        for (int k = 0; k < 5; k++) {
            float2 acc = a[0];
#pragma unroll
            for (int j = 1; j < 5; j++) {
                float2 w5 = twd<SIGN>(tw, 64 * ((j * k) % 5));
                float2 pr = cmulf(a[j], w5);
                acc.x += pr.x; acc.y += pr.y;
            }
            float2 wt = twd<SIGN>(tw, p * k);
            Y[5 * p + k] = cmulf(acc, wt);
        }
    }
    __syncthreads();
    stage4<SIGN, 64, 5>(Y, X, tw, t);
    __syncthreads();
    stage4<SIGN, 16, 20>(X, Y, tw, t);
    __syncthreads();
    stage4<SIGN, 4, 80>(Y, X, tw, t);
    __syncthreads();
}

// ---------------------------- init kernels ---------------------------------
__global__ void k_tw() {
    int j = threadIdx.x;
    if (j < 320) {
        double th = -2.0 * 3.14159265358979323846 * (double)j / 320.0;
        g_tw[j] = make_float2((float)cos(th), (float)sin(th));
    }
}

__global__ void k_lut(const float* __restrict__ w, const float* __restrict__ mu,
                      const float* __restrict__ sigma) {
    int f = blockIdx.x;
    float inv2s2 = 1.0f / (2.0f * sigma[0] * sigma[0]);
    for (int t = threadIdx.x; t < NLUT; t += blockDim.x) {
        float x = LUT_MIN + LUT_SPAN * (float)t / (float)(NLUT - 1);
        float acc = 0.0f;
        for (int i = 0; i < 31; i++) {
            float d = x - mu[i];
            acc += w[f * 31 + i] * expf(-d * d * inv2s2);
        }
        g_lut[f * NLUT + t] = acc;
    }
}

__global__ void k_pad(const float* __restrict__ u) {
    int idx = blockIdx.x * blockDim.x + threadIdx.x;
    if (idx >= NB * HP * HP) return;
    int x = idx % HP, y = (idx / HP) % HP, n = idx / (HP * HP);
    int sy = y - 11; sy = (sy < 0) ? -sy : ((sy > 319) ? 638 - sy : sy);
    int sx = x - 11; sx = (sx < 0) ? -sx : ((sx > 319) ? 638 - sx : sx);
    g_upad[idx] = ((const float2*)u)[(n * HH + sy) * WW + sx];
}

// ------------- forward conv (2ch -> 32, 2 features/block) + RBF-LUT --------
// tile: 32 rows x 64 cols, blockIdx.z = (n, feature-pair), 256 threads.
// sIn shared by both features; weights as ulonglong2 -> one LDS.128;
// two accumulator banks. Carveout raised host-side for occupancy.
#define CST 77
__global__ __launch_bounds__(256) void k_conv(const float* __restrict__ ck) {
    __shared__ unsigned long long sIn[42 * CST];   // packed (re,im)  ~25.9KB
    __shared__ float sLut[2][NLUT];                // 16KB
    __shared__ ulonglong2 sK[121];                 // {wA(re,im), wB(re,im)}
    int nf2 = blockIdx.z, n = nf2 >> 4, fp = nf2 & 15;
    int fA = fp * 2, fB = fA + 1;
    int y0 = blockIdx.y * 32, x0 = blockIdx.x * 64;
    int tid = threadIdx.x;
    for (int i = tid; i < NLUT; i += 256) {
        sLut[0][i] = g_lut[fA * NLUT + i];
        sLut[1][i] = g_lut[fB * NLUT + i];
    }
    const float2* ck2 = (const float2*)ck;
    if (tid < 121) {
        float2 wa = ck2[fA * 121 + tid];
        float2 wb = ck2[fB * 121 + tid];
        sK[tid] = make_ulonglong2(pack2(wa.x, wa.y), pack2(wb.x, wb.y));
    }
    for (int i = tid; i < 42 * CST; i += 256) {
        int ly = i / CST, lx = i % CST;
        int gy = y0 + ly - 5, gx = x0 + lx - 5;
        float2 v = make_float2(0.f, 0.f);
        if (lx < 74 && (unsigned)gy < (unsigned)HP && (unsigned)gx < (unsigned)HP)
            v = g_upad[(n * HP + gy) * HP + gx];
        sIn[i] = pack2(v.x, v.y);
    }
    __syncthreads();
    int ty = tid & 31, txg = (tid >> 5) << 3;   // 32 rows x (8 groups * 8 cols)
    unsigned long long accA[8], accB[8];
#pragma unroll
    for (int j = 0; j < 8; j++) { accA[j] = 0ull; accB[j] = 0ull; }
#pragma unroll 1
    for (int ky = 0; ky < 11; ky++) {
        unsigned long long v[18];
        const unsigned long long* rowp = &sIn[(ty + ky) * CST + txg];
#pragma unroll
        for (int p = 0; p < 18; p++) v[p] = rowp[p];
#pragma unroll
        for (int kx = 0; kx < 11; kx++) {
            ulonglong2 wv = sK[ky * 11 + kx];
#pragma unroll
            for (int j = 0; j < 8; j++) {
                fma2(accA[j], v[kx + j], wv.x);
                fma2(accB[j], v[kx + j], wv.y);
            }
        }
    }
    __syncthreads();                 // sIn reads done; reuse as staging
    float* sOut = (float*)sIn;       // 2 planes of 32 x 65 floats
#pragma unroll
    for (int j = 0; j < 8; j++) {
        float lo, hi;
        unpack2(accA[j], lo, hi);
        float a = lo + hi;
        float tpos = (a - LUT_MIN) * LUT_SCALE;
        tpos = fminf(fmaxf(tpos, 0.f), (float)(NLUT - 1) - 0.001f);
        int ii = (int)tpos;
        float fr = tpos - (float)ii;
        sOut[ty * 65 + txg + j] = sLut[0][ii] + fr * (sLut[0][ii + 1] - sLut[0][ii]);
        unpack2(accB[j], lo, hi);
        a = lo + hi;
        tpos = (a - LUT_MIN) * LUT_SCALE;
        tpos = fminf(fmaxf(tpos, 0.f), (float)(NLUT - 1) - 0.001f);
        ii = (int)tpos;
        fr = tpos - (float)ii;
        sOut[2080 + ty * 65 + txg + j] = sLut[1][ii] + fr * (sLut[1][ii + 1] - sLut[1][ii]);
    }
    __syncthreads();
    for (int i = tid; i < 32 * 64; i += 256) {
        int row = i >> 6, col = i & 63;
        int y = y0 + row, x = x0 + col;
        if (y < HP && x < HP) {
            g_fuk[((n * NF + fA) * HP + y) * HP + x] = sOut[row * 65 + col];
            g_fuk[((n * NF + fB) * HP + y) * HP + x] = sOut[2080 + row * 65 + col];
        }
    }
}

// ----------------------------- FFT passes ----------------------------------
__global__ void k_fft_row_fwd(const float* __restrict__ u,
                              const float* __restrict__ cs) {
    __shared__ float2 sm[4][2][320];
    __shared__ float2 sTw[320];
    int tid = threadIdx.x;
    sTw[tid] = g_tw[tid];
    int g = tid / 80, t = tid % 80;
    int rowIdx = blockIdx.x * 4 + g;
    int r = rowIdx % HH, nc = rowIdx / HH;
    int n = nc / NCOIL;
    const float2* up = (const float2*)u + (n * HH + r) * WW;
    const float2* cp = (const float2*)cs + (nc * HH + r) * WW;
    float2* X = &sm[g][0][0];
    float2* Y = &sm[g][1][0];
    for (int x = t; x < 320; x += 80) {
        float2 q = cmulf(up[x], cp[x]);
        float sgn = ((r + x) & 1) ? -1.f : 1.f;
        X[x] = make_float2(sgn * q.x, sgn * q.y);
    }
    __syncthreads();
    fft320<-1>(X, Y, sTw, t);
    float2* dst = g_work + nc * (HH * WW) + r * WW;
    const float sc = 1.f / 320.f;
    for (int x = t; x < 320; x += 80)
        dst[x] = make_float2(X[x].x * sc, X[x].y * sc);
}

__global__ void k_fft_col_fwd(const float* __restrict__ fdat,
                              const float* __restrict__ mask) {
    __shared__ float2 sm[4][2][320];
    __shared__ float2 sTw[320];
    int tid = threadIdx.x;
    sTw[tid] = g_tw[tid];
    int blk = blockIdx.x;
    int nc = blk / 80, cb = (blk % 80) * 4;
    int n = nc / NCOIL;
    float2* base = g_work + nc * (HH * WW);
    for (int i = tid; i < 1280; i += 320) {
        int row = i >> 2, cc = i & 3;
        sm[cc][0][row] = base[row * WW + cb + cc];
    }
    __syncthreads();
    int g = tid / 80, t = tid % 80;
    fft320<-1>(&sm[g][0][0], &sm[g][1][0], sTw, t);
    const float2* f2 = (const float2*)fdat + nc * (HH * WW);
    for (int i = tid; i < 1280; i += 320) {
        int row = i >> 2, cc = i & 3;
        int col = cb + cc;
        float m = mask[n * (HH * WW) + row * WW + col];
        float2 fv = f2[row * WW + col];
        float sgn = ((row + col) & 1) ? -1.f : 1.f;
        float2 q = sm[cc][0][row];
        base[row * WW + col] =
            make_float2(m * (q.x - sgn * fv.x), m * (q.y - sgn * fv.y));
    }
}

__global__ void k_fft_row_inv() {
    __shared__ float2 sm[4][2][320];
    __shared__ float2 sTw[320];
    int tid = threadIdx.x;
    sTw[tid] = g_tw[tid];
    int g = tid / 80, t = tid % 80;
    int rowIdx = blockIdx.x * 4 + g;
    int r = rowIdx % HH, nc = rowIdx / HH;
    float2* rowp = g_work + nc * (HH * WW) + r * WW;
    float2* X = &sm[g][0][0];
    float2* Y = &sm[g][1][0];
    for (int x = t; x < 320; x += 80) X[x] = rowp[x];
    __syncthreads();
    fft320<1>(X, Y, sTw, t);
    const float sc = 1.f / 320.f;
    for (int x = t; x < 320; x += 80)
        rowp[x] = make_float2(X[x].x * sc, X[x].y * sc);
}

// --- fused: columns inverse over ALL 15 coils + coil-sum + final combine ---
// grid: NB*80 blocks (n, 4-column group), 320 threads.
// du accumulated in registers across coils; then out = u - Ru/32 - lam*Du.
__global__ void k_col_inv_comb(const float* __restrict__ cs,
                               const float* __restrict__ u,
                               const float* __restrict__ lamb,
                               float2* __restrict__ out) {
    __shared__ float2 sm[4][2][320];
    __shared__ float2 sTw[320];
    int tid = threadIdx.x;
    sTw[tid] = g_tw[tid];
    int blk = blockIdx.x;
    int n = blk / 80, cb = (blk % 80) * 4;
    int g = tid / 80, t = tid % 80;
    float2 du[4];
#pragma unroll
    for (int k = 0; k < 4; k++) du[k] = make_float2(0.f, 0.f);
#pragma unroll 1
    for (int c = 0; c < NCOIL; c++) {
        int nc = n * NCOIL + c;
        __syncthreads();   // protect sm reuse across iterations
        float2* base = g_work + nc * (HH * WW);
        for (int i = tid; i < 1280; i += 320) {
            int row = i >> 2, cc = i & 3;
            sm[cc][0][row] = base[row * WW + cb + cc];
        }
        __syncthreads();
        fft320<1>(&sm[g][0][0], &sm[g][1][0], sTw, t);
        const float2* c2 = (const float2*)cs + nc * (HH * WW);
#pragma unroll
        for (int k = 0; k < 4; k++) {
            int i = tid + 320 * k;
            int row = i >> 2, cc = i & 3;
            int col = cb + cc;
            float2 v = sm[cc][0][row];
            float2 cv = c2[row * WW + col];
            float sgn = ((row + col) & 1) ? -1.f : 1.f;
            du[k].x += sgn * (v.x * cv.x + v.y * cv.y);
            du[k].y += sgn * (v.y * cv.x - v.x * cv.y);
        }
    }
    float lam = lamb[0];
#pragma unroll
    for (int k = 0; k < 4; k++) {
        int i = tid + 320 * k;
        int row = i >> 2, cc = i & 3;
        int col = cb + cc;
        int pix = row * WW + col;
        float2 ru = make_float2(0.f, 0.f);
#pragma unroll
        for (int ch = 0; ch < 4; ch++) {
            float2 v = g_adj[(ch * NB + n) * (HH * WW) + pix];
            ru.x += v.x; ru.y += v.y;
        }
        float2 uu = ((const float2*)u)[n * (HH * WW) + pix];
        float2 o;
        o.x = uu.x - ru.x * (1.f / 32.f) - lam * du[k].x;
        o.y = uu.y - ru.y * (1.f / 32.f) - lam * du[k].y;
        out[n * (HH * WW) + pix] = o;
    }
}

// ----------------- adjoint conv partials (feature-paired) ------------------
#define FST 77
__global__ __launch_bounds__(128) void k_adj(const float* __restrict__ ck) {
    __shared__ unsigned long long sT[26 * FST];      // 16KB
    __shared__ ulonglong2 sK[121];                   // {(wreA,wreB),(wimA,wimB)}
    int zz = blockIdx.z, n = zz >> 2, chunk = zz & 3;
    int y0 = blockIdx.y * 16, x0 = blockIdx.x * 64;
    int tid = threadIdx.x;
    int ty = tid & 15, txg = (tid >> 4) << 3;   // 16 rows x (8 groups * 8 cols)
    unsigned long long accre[8], accim[8];
#pragma unroll
    for (int j = 0; j < 8; j++) { accre[j] = 0ull; accim[j] = 0ull; }
    const float2* ck2 = (const float2*)ck;
#pragma unroll 1
    for (int p = 0; p < 4; p++) {
        int fA = (chunk * 4 + p) * 2, fB = fA + 1;
        __syncthreads();
        const float* baseA = &g_fuk[(n * NF + fA) * HP * HP];
        const float* baseB = &g_fuk[(n * NF + fB) * HP * HP];
        for (int i = tid; i < 26 * FST; i += 128) {
            int ly = i / FST, lx = i % FST;
            float vA = 0.f, vB = 0.f;
            if (lx < 74) {
                int off = (y0 + 6 + ly) * HP + (x0 + 6 + lx);
                vA = baseA[off];
                vB = baseB[off];
            }
            sT[i] = pack2(vA, vB);
        }
        if (tid < 121) {
            float2 wA = ck2[fA * 121 + 120 - tid];   // reversed kernel
            float2 wB = ck2[fB * 121 + 120 - tid];
            sK[tid] = make_ulonglong2(pack2(wA.x, wB.x), pack2(wA.y, wB.y));
        }
        __syncthreads();
#pragma unroll 1
        for (int ky = 0; ky < 11; ky++) {
            unsigned long long v[18];
            const unsigned long long* rowp = &sT[(ty + ky) * FST + txg];
#pragma unroll
            for (int q = 0; q < 18; q++) v[q] = rowp[q];
#pragma unroll
            for (int kx = 0; kx < 11; kx++) {
                ulonglong2 wv = sK[ky * 11 + kx];
#pragma unroll
                for (int j = 0; j < 8; j++) {
                    fma2(accre[j], v[kx + j], wv.x);
                    fma2(accim[j], v[kx + j], wv.y);
                }
            }
        }
    }
    int y = y0 + ty;
    float2* dst = &g_adj[((chunk * NB + n) * HH + y) * WW + x0 + txg];
#pragma unroll
    for (int j = 0; j < 8; j++) {
        float a, b, c, d;
        unpack2(accre[j], a, b);
        unpack2(accim[j], c, d);
        dst[j] = make_float2(a + b, c + d);
    }
}

// ---------------------------------------------------------------------------
extern "C" void kernel_launch(void* const* d_in, const int* in_sizes, int n_in,
                              void* d_out, int out_size) {
    const float* u_t   = (const float*)d_in[0];
    const float* fdat  = (const float*)d_in[1];
    const float* cs    = (const float*)d_in[2];
    const float* mask  = (const float*)d_in[3];
    const float* ck    = (const float*)d_in[4];
    const float* w     = (const float*)d_in[5];
    const float* mu    = (const float*)d_in[6];
    const float* sigma = (const float*)d_in[7];
    const float* lamb  = (const float*)d_in[8];
    float2* out = (float2*)d_out;

    // raise smem carveout so 5 blocks of k_conv fit (idempotent, no alloc)
    cudaFuncSetAttribute(k_conv,
        cudaFuncAttributePreferredSharedMemoryCarveout, 100);

    k_tw<<<1, 320>>>();
    k_lut<<<NF, 256>>>(w, mu, sigma);
    k_pad<<<(NB * HP * HP + 255) / 256, 256>>>(u_t);
    k_conv<<<dim3(6, 11, NB * 16), 256>>>(ck);

    int nrows = NB * NCOIL * HH;          // 19200
    k_fft_row_fwd<<<nrows / 4, 320>>>(u_t, cs);
    k_fft_col_fwd<<<NB * NCOIL * 80, 320>>>(fdat, mask);
    k_fft_row_inv<<<nrows / 4, 320>>>();

    k_adj<<<dim3(5, 20, NB * 4), 128>>>(ck);
    k_col_inv_comb<<<NB * 80, 320>>>(cs, u_t, lamb, out);
}

// round 15
// speedup vs baseline: 1.0574x; 1.0574x over previous
#include <cuda_runtime.h>
#include <math.h>

#define NB 4
#define NCOIL 15
#define HH 320
#define WW 320
#define NF 32
#define KS 11
#define HP 342          // 320 + 2*11
#define NLUT 2048
#define LUT_MIN (-1.6f)
#define LUT_SPAN (3.2f)
#define LUT_SCALE ((float)(NLUT - 1) / LUT_SPAN)

// -------- scratch (device globals; no runtime allocation allowed) ----------
__device__ float2 g_upad[NB * HP * HP];            // ~3.7 MB
__device__ float  g_fuk[NB * NF * HP * HP];        // ~60 MB
__device__ float2 g_work[NB * NCOIL * HH * WW];    // ~49 MB
__device__ float2 g_adj[4 * NB * HH * WW];         // 13.1 MB adjoint partials
__device__ float  g_lut[NF * NLUT];
__device__ float2 g_tw[320];                       // W320^j = e^{-2pi i j/320}

// ---------------------------------------------------------------------------
__device__ __forceinline__ float2 cmulf(float2 a, float2 b) {
    return make_float2(fmaf(a.x, b.x, -(a.y * b.y)), fmaf(a.x, b.y, a.y * b.x));
}

// ---- packed f32x2 helpers ----
__device__ __forceinline__ unsigned long long pack2(float x, float y) {
    unsigned long long r;
    asm("mov.b64 %0, {%1,%2};" : "=l"(r) : "f"(x), "f"(y));
    return r;
}
__device__ __forceinline__ void unpack2(unsigned long long v, float& x, float& y) {
    asm("mov.b64 {%0,%1}, %2;" : "=f"(x), "=f"(y) : "l"(v));
}
__device__ __forceinline__ void fma2(unsigned long long& acc,
                                     unsigned long long a, unsigned long long b) {
    asm("fma.rn.f32x2 %0, %1, %2, %0;" : "+l"(acc) : "l"(a), "l"(b));
}

template <int SIGN>
__device__ __forceinline__ float2 twd(const float2* tw, int idx) {
    float2 t = tw[idx];
    return make_float2(t.x, (SIGN < 0) ? t.y : -t.y);
}

// One radix-4 Stockham stage: total length 320 = n*s, n divisible by 4.
template <int SIGN, int n, int s>
__device__ __forceinline__ void stage4(const float2* __restrict__ src,
                                       float2* __restrict__ dst,
                                       const float2* tw, int t) {
    const int m = n / 4;
    const int stride = 320 / n;
    int p = t % m, q = t / m;        // m*s == 80 for all stages used
    float2 a0 = src[q + s * (p + 0 * m)];
    float2 a1 = src[q + s * (p + 1 * m)];
    float2 a2 = src[q + s * (p + 2 * m)];
    float2 a3 = src[q + s * (p + 3 * m)];
    float2 t0 = make_float2(a0.x + a2.x, a0.y + a2.y);
    float2 t1 = make_float2(a0.x - a2.x, a0.y - a2.y);
    float2 t2 = make_float2(a1.x + a3.x, a1.y + a3.y);
    float2 t3 = make_float2(a1.x - a3.x, a1.y - a3.y);
    float2 it3 = make_float2(-t3.y, t3.x);          // i * t3
    float2 A0 = make_float2(t0.x + t2.x, t0.y + t2.y);
    float2 A2 = make_float2(t0.x - t2.x, t0.y - t2.y);
    float2 A1 = make_float2(t1.x + SIGN * it3.x, t1.y + SIGN * it3.y);
    float2 A3 = make_float2(t1.x - SIGN * it3.x, t1.y - SIGN * it3.y);
    dst[q + s * (4 * p + 0)] = A0;
    dst[q + s * (4 * p + 1)] = cmulf(A1, twd<SIGN>(tw, p * stride));
    dst[q + s * (4 * p + 2)] = cmulf(A2, twd<SIGN>(tw, 2 * p * stride));
    dst[q + s * (4 * p + 3)] = cmulf(A3, twd<SIGN>(tw, 3 * p * stride));
}

// 320-point Stockham FFT (radices 5,4,4,4). X,Y: smem buffers (len 320).
template <int SIGN>
__device__ void fft320(float2* X, float2* Y, const float2* tw, int t) {
    if (t < 64) {
        int p = t;
        float2 a[5];
#pragma unroll
        for (int j = 0; j < 5; j++) a[j] = X[p + 64 * j];
#pragma unroll
        for (int k = 0; k < 5; k++) {
            float2 acc = a[0];
#pragma unroll
            for (int j = 1; j < 5; j++) {
                float2 w5 = twd<SIGN>(tw, 64 * ((j * k) % 5));
                float2 pr = cmulf(a[j], w5);
                acc.x += pr.x; acc.y += pr.y;
            }
            float2 wt = twd<SIGN>(tw, p * k);
            Y[5 * p + k] = cmulf(acc, wt);
        }
    }
    __syncthreads();
    stage4<SIGN, 64, 5>(Y, X, tw, t);
    __syncthreads();
    stage4<SIGN, 16, 20>(X, Y, tw, t);
    __syncthreads();
    stage4<SIGN, 4, 80>(Y, X, tw, t);
    __syncthreads();
}

// ---------------------------- init kernels ---------------------------------
__global__ void k_tw() {
    int j = threadIdx.x;
    if (j < 320) {
        double th = -2.0 * 3.14159265358979323846 * (double)j / 320.0;
        g_tw[j] = make_float2((float)cos(th), (float)sin(th));
    }
}

__global__ void k_lut(const float* __restrict__ w, const float* __restrict__ mu,
                      const float* __restrict__ sigma) {
    int f = blockIdx.x;
    float inv2s2 = 1.0f / (2.0f * sigma[0] * sigma[0]);
    for (int t = threadIdx.x; t < NLUT; t += blockDim.x) {
        float x = LUT_MIN + LUT_SPAN * (float)t / (float)(NLUT - 1);
        float acc = 0.0f;
        for (int i = 0; i < 31; i++) {
            float d = x - mu[i];
            acc += w[f * 31 + i] * expf(-d * d * inv2s2);
        }
        g_lut[f * NLUT + t] = acc;
    }
}

__global__ void k_pad(const float* __restrict__ u) {
    int idx = blockIdx.x * blockDim.x + threadIdx.x;
    if (idx >= NB * HP * HP) return;
    int x = idx % HP, y = (idx / HP) % HP, n = idx / (HP * HP);
    int sy = y - 11; sy = (sy < 0) ? -sy : ((sy > 319) ? 638 - sy : sy);
    int sx = x - 11; sx = (sx < 0) ? -sx : ((sx > 319) ? 638 - sx : sx);
    g_upad[idx] = ((const float2*)u)[(n * HH + sy) * WW + sx];
}

// ------------- forward conv (2ch -> 32, 2 features/block) + RBF-LUT --------
// tile: 32 rows x 64 cols, blockIdx.z = (n, feature-pair), 256 threads.
// __launch_bounds__(256,4): cap at 64 regs so 4 blocks fill the 64K RF
// exactly -> 32 warps/SM (was reg-limited to 3 blocks at 66 regs).
#define CST 77
__global__ __launch_bounds__(256, 4) void k_conv(const float* __restrict__ ck) {
    __shared__ unsigned long long sIn[42 * CST];   // packed (re,im)  ~25.9KB
    __shared__ float sLut[2][NLUT];                // 16KB
    __shared__ ulonglong2 sK[121];                 // {wA(re,im), wB(re,im)}
    int nf2 = blockIdx.z, n = nf2 >> 4, fp = nf2 & 15;
    int fA = fp * 2, fB = fA + 1;
    int y0 = blockIdx.y * 32, x0 = blockIdx.x * 64;
    int tid = threadIdx.x;
    for (int i = tid; i < NLUT; i += 256) {
        sLut[0][i] = g_lut[fA * NLUT + i];
        sLut[1][i] = g_lut[fB * NLUT + i];
    }
    const float2* ck2 = (const float2*)ck;
    if (tid < 121) {
        float2 wa = ck2[fA * 121 + tid];
        float2 wb = ck2[fB * 121 + tid];
        sK[tid] = make_ulonglong2(pack2(wa.x, wa.y), pack2(wb.x, wb.y));
    }
    for (int i = tid; i < 42 * CST; i += 256) {
        int ly = i / CST, lx = i % CST;
        int gy = y0 + ly - 5, gx = x0 + lx - 5;
        float2 v = make_float2(0.f, 0.f);
        if (lx < 74 && (unsigned)gy < (unsigned)HP && (unsigned)gx < (unsigned)HP)
            v = g_upad[(n * HP + gy) * HP + gx];
        sIn[i] = pack2(v.x, v.y);
    }
    __syncthreads();
    int ty = tid & 31, txg = (tid >> 5) << 3;   // 32 rows x (8 groups * 8 cols)
    unsigned long long accA[8], accB[8];
#pragma unroll
    for (int j = 0; j < 8; j++) { accA[j] = 0ull; accB[j] = 0ull; }
#pragma unroll 1
    for (int ky = 0; ky < 11; ky++) {
        unsigned long long v[18];
        const unsigned long long* rowp = &sIn[(ty + ky) * CST + txg];
#pragma unroll
        for (int p = 0; p < 18; p++) v[p] = rowp[p];
#pragma unroll
        for (int kx = 0; kx < 11; kx++) {
            ulonglong2 wv = sK[ky * 11 + kx];
#pragma unroll
            for (int j = 0; j < 8; j++) {
                fma2(accA[j], v[kx + j], wv.x);
                fma2(accB[j], v[kx + j], wv.y);
            }
        }
    }
    __syncthreads();                 // sIn reads done; reuse as staging
    float* sOut = (float*)sIn;       // 2 planes of 32 x 65 floats
#pragma unroll
    for (int j = 0; j < 8; j++) {
        float lo, hi;
        unpack2(accA[j], lo, hi);
        float a = lo + hi;
        float tpos = (a - LUT_MIN) * LUT_SCALE;
        tpos = fminf(fmaxf(tpos, 0.f), (float)(NLUT - 1) - 0.001f);
        int ii = (int)tpos;
        float fr = tpos - (float)ii;
        sOut[ty * 65 + txg + j] = sLut[0][ii] + fr * (sLut[0][ii + 1] - sLut[0][ii]);
        unpack2(accB[j], lo, hi);
        a = lo + hi;
        tpos = (a - LUT_MIN) * LUT_SCALE;
        tpos = fminf(fmaxf(tpos, 0.f), (float)(NLUT - 1) - 0.001f);
        ii = (int)tpos;
        fr = tpos - (float)ii;
        sOut[2080 + ty * 65 + txg + j] = sLut[1][ii] + fr * (sLut[1][ii + 1] - sLut[1][ii]);
    }
    __syncthreads();
    for (int i = tid; i < 32 * 64; i += 256) {
        int row = i >> 6, col = i & 63;
        int y = y0 + row, x = x0 + col;
        if (y < HP && x < HP) {
            g_fuk[((n * NF + fA) * HP + y) * HP + x] = sOut[row * 65 + col];
            g_fuk[((n * NF + fB) * HP + y) * HP + x] = sOut[2080 + row * 65 + col];
        }
    }
}

// ----------------------------- FFT passes ----------------------------------
__global__ void k_fft_row_fwd(const float* __restrict__ u,
                              const float* __restrict__ cs) {
    __shared__ float2 sm[4][2][320];
    __shared__ float2 sTw[320];
    int tid = threadIdx.x;
    sTw[tid] = g_tw[tid];
    int g = tid / 80, t = tid % 80;
    int rowIdx = blockIdx.x * 4 + g;
    int r = rowIdx % HH, nc = rowIdx / HH;
    int n = nc / NCOIL;
    const float2* up = (const float2*)u + (n * HH + r) * WW;
    const float2* cp = (const float2*)cs + (nc * HH + r) * WW;
    float2* X = &sm[g][0][0];
    float2* Y = &sm[g][1][0];
    for (int x = t; x < 320; x += 80) {
        float2 q = cmulf(up[x], cp[x]);
        float sgn = ((r + x) & 1) ? -1.f : 1.f;
        X[x] = make_float2(sgn * q.x, sgn * q.y);
    }
    __syncthreads();
    fft320<-1>(X, Y, sTw, t);
    float2* dst = g_work + nc * (HH * WW) + r * WW;
    const float sc = 1.f / 320.f;
    for (int x = t; x < 320; x += 80)
        dst[x] = make_float2(X[x].x * sc, X[x].y * sc);
}

__global__ void k_fft_col_fwd(const float* __restrict__ fdat,
                              const float* __restrict__ mask) {
    __shared__ float2 sm[4][2][320];
    __shared__ float2 sTw[320];
    int tid = threadIdx.x;
    sTw[tid] = g_tw[tid];
    int blk = blockIdx.x;
    int nc = blk / 80, cb = (blk % 80) * 4;
    int n = nc / NCOIL;
    float2* base = g_work + nc * (HH * WW);
    for (int i = tid; i < 1280; i += 320) {
        int row = i >> 2, cc = i & 3;
        sm[cc][0][row] = base[row * WW + cb + cc];
    }
    __syncthreads();
    int g = tid / 80, t = tid % 80;
    fft320<-1>(&sm[g][0][0], &sm[g][1][0], sTw, t);
    const float2* f2 = (const float2*)fdat + nc * (HH * WW);
    for (int i = tid; i < 1280; i += 320) {
        int row = i >> 2, cc = i & 3;
        int col = cb + cc;
        float m = mask[n * (HH * WW) + row * WW + col];
        float2 fv = f2[row * WW + col];
        float sgn = ((row + col) & 1) ? -1.f : 1.f;
        float2 q = sm[cc][0][row];
        base[row * WW + col] =
            make_float2(m * (q.x - sgn * fv.x), m * (q.y - sgn * fv.y));
    }
}

__global__ void k_fft_row_inv() {
    __shared__ float2 sm[4][2][320];
    __shared__ float2 sTw[320];
    int tid = threadIdx.x;
    sTw[tid] = g_tw[tid];
    int g = tid / 80, t = tid % 80;
    int rowIdx = blockIdx.x * 4 + g;
    int r = rowIdx % HH, nc = rowIdx / HH;
    float2* rowp = g_work + nc * (HH * WW) + r * WW;
    float2* X = &sm[g][0][0];
    float2* Y = &sm[g][1][0];
    for (int x = t; x < 320; x += 80) X[x] = rowp[x];
    __syncthreads();
    fft320<1>(X, Y, sTw, t);
    const float sc = 1.f / 320.f;
    for (int x = t; x < 320; x += 80)
        rowp[x] = make_float2(X[x].x * sc, X[x].y * sc);
}

__global__ void k_fft_col_inv(const float* __restrict__ cs) {
    __shared__ float2 sm[4][2][320];
    __shared__ float2 sTw[320];
    int tid = threadIdx.x;
    sTw[tid] = g_tw[tid];
    int blk = blockIdx.x;
    int nc = blk / 80, cb = (blk % 80) * 4;
    float2* base = g_work + nc * (HH * WW);
    for (int i = tid; i < 1280; i += 320) {
        int row = i >> 2, cc = i & 3;
        sm[cc][0][row] = base[row * WW + cb + cc];
    }
    __syncthreads();
    int g = tid / 80, t = tid % 80;
    fft320<1>(&sm[g][0][0], &sm[g][1][0], sTw, t);
    const float2* c2 = (const float2*)cs + nc * (HH * WW);
    for (int i = tid; i < 1280; i += 320) {
        int row = i >> 2, cc = i & 3;
        int col = cb + cc;
        float2 v = sm[cc][0][row];
        float2 cv = c2[row * WW + col];
        float sgn = ((row + col) & 1) ? -1.f : 1.f;
        float2 o;
        o.x = sgn * (v.x * cv.x + v.y * cv.y);
        o.y = sgn * (v.y * cv.x - v.x * cv.y);
        base[row * WW + col] = o;
    }
}

// ----------------- adjoint conv partials (feature-paired) ------------------
#define FST 77
__global__ __launch_bounds__(128) void k_adj(const float* __restrict__ ck) {
    __shared__ unsigned long long sT[26 * FST];      // 16KB
    __shared__ ulonglong2 sK[121];                   // {(wreA,wreB),(wimA,wimB)}
    int zz = blockIdx.z, n = zz >> 2, chunk = zz & 3;
    int y0 = blockIdx.y * 16, x0 = blockIdx.x * 64;
    int tid = threadIdx.x;
    int ty = tid & 15, txg = (tid >> 4) << 3;   // 16 rows x (8 groups * 8 cols)
    unsigned long long accre[8], accim[8];
#pragma unroll
    for (int j = 0; j < 8; j++) { accre[j] = 0ull; accim[j] = 0ull; }
    const float2* ck2 = (const float2*)ck;
#pragma unroll 1
    for (int p = 0; p < 4; p++) {
        int fA = (chunk * 4 + p) * 2, fB = fA + 1;
        __syncthreads();
        const float* baseA = &g_fuk[(n * NF + fA) * HP * HP];
        const float* baseB = &g_fuk[(n * NF + fB) * HP * HP];
        for (int i = tid; i < 26 * FST; i += 128) {
            int ly = i / FST, lx = i % FST;
            float vA = 0.f, vB = 0.f;
            if (lx < 74) {
                int off = (y0 + 6 + ly) * HP + (x0 + 6 + lx);
                vA = baseA[off];
                vB = baseB[off];
            }
            sT[i] = pack2(vA, vB);
        }
        if (tid < 121) {
            float2 wA = ck2[fA * 121 + 120 - tid];   // reversed kernel
            float2 wB = ck2[fB * 121 + 120 - tid];
            sK[tid] = make_ulonglong2(pack2(wA.x, wB.x), pack2(wA.y, wB.y));
        }
        __syncthreads();
#pragma unroll 1
        for (int ky = 0; ky < 11; ky++) {
            unsigned long long v[18];
            const unsigned long long* rowp = &sT[(ty + ky) * FST + txg];
#pragma unroll
            for (int q = 0; q < 18; q++) v[q] = rowp[q];
#pragma unroll
            for (int kx = 0; kx < 11; kx++) {
                ulonglong2 wv = sK[ky * 11 + kx];
#pragma unroll
                for (int j = 0; j < 8; j++) {
                    fma2(accre[j], v[kx + j], wv.x);
                    fma2(accim[j], v[kx + j], wv.y);
                }
            }
        }
    }
    int y = y0 + ty;
    float2* dst = &g_adj[((chunk * NB + n) * HH + y) * WW + x0 + txg];
#pragma unroll
    for (int j = 0; j < 8; j++) {
        float a, b, c, d;
        unpack2(accre[j], a, b);
        unpack2(accim[j], c, d);
        dst[j] = make_float2(a + b, c + d);
    }
}

// ------------- final combine: u - Ru - Du  (memory-light) ------------------
__global__ void k_combine(const float* __restrict__ u,
                          const float* __restrict__ lamb,
                          float2* __restrict__ out) {
    int idx = blockIdx.x * blockDim.x + threadIdx.x;
    if (idx >= NB * HH * WW) return;
    int pix = idx % (HH * WW), n = idx / (HH * WW);
    float lam = lamb[0];
    float2 ru = make_float2(0.f, 0.f);
#pragma unroll
    for (int c = 0; c < 4; c++) {
        float2 v = g_adj[(c * NB + n) * (HH * WW) + pix];
        ru.x += v.x; ru.y += v.y;
    }
    float2 du = make_float2(0.f, 0.f);
#pragma unroll 1
    for (int c = 0; c < NCOIL; c++) {
        float2 v = g_work[(n * NCOIL + c) * (HH * WW) + pix];
        du.x += v.x; du.y += v.y;
    }
    float2 uu = ((const float2*)u)[idx];
    float2 o;
    o.x = uu.x - ru.x * (1.f / 32.f) - lam * du.x;
    o.y = uu.y - ru.y * (1.f / 32.f) - lam * du.y;
    out[idx] = o;
}

// ---------------------------------------------------------------------------
extern "C" void kernel_launch(void* const* d_in, const int* in_sizes, int n_in,
                              void* d_out, int out_size) {
    const float* u_t   = (const float*)d_in[0];
    const float* fdat  = (const float*)d_in[1];
    const float* cs    = (const float*)d_in[2];
    const float* mask  = (const float*)d_in[3];
    const float* ck    = (const float*)d_in[4];
    const float* w     = (const float*)d_in[5];
    const float* mu    = (const float*)d_in[6];
    const float* sigma = (const float*)d_in[7];
    const float* lamb  = (const float*)d_in[8];
    float2* out = (float2*)d_out;

    // smem carveout: 4 blocks x 44.2KB of k_conv need ~177KB on-SM
    cudaFuncSetAttribute(k_conv,
        cudaFuncAttributePreferredSharedMemoryCarveout, 100);

    k_tw<<<1, 320>>>();
    k_lut<<<NF, 256>>>(w, mu, sigma);
    k_pad<<<(NB * HP * HP + 255) / 256, 256>>>(u_t);
    k_conv<<<dim3(6, 11, NB * 16), 256>>>(ck);

    int nrows = NB * NCOIL * HH;          // 19200
    k_fft_row_fwd<<<nrows / 4, 320>>>(u_t, cs);
    k_fft_col_fwd<<<NB * NCOIL * 80, 320>>>(fdat, mask);
    k_fft_row_inv<<<nrows / 4, 320>>>();
    k_fft_col_inv<<<NB * NCOIL * 80, 320>>>(cs);

    k_adj<<<dim3(5, 20, NB * 4), 128>>>(ck);
    k_combine<<<(NB * HH * WW + 255) / 256, 256>>>(u_t, lamb, out);
}

// round 16
// speedup vs baseline: 1.1042x; 1.0443x over previous
#include <cuda_runtime.h>
#include <math.h>

#define NB 4
#define NCOIL 15
#define HH 320
#define WW 320
#define NF 32
#define KS 11
#define HP 342          // 320 + 2*11
#define NLUT 2048
#define LUT_MIN (-1.6f)
#define LUT_SPAN (3.2f)
#define LUT_SCALE ((float)(NLUT - 1) / LUT_SPAN)

typedef unsigned long long u64;

// -------- scratch (device globals; no runtime allocation allowed) ----------
__device__ float2 g_upad[NB * HP * HP];                      // ~3.7 MB
__device__ float  g_fuk[NB * NF * HP * HP];                  // ~60 MB
__device__ __align__(16) float2 g_work[NB * NCOIL * HH * WW];// ~49 MB
__device__ float2 g_adj[4 * NB * HH * WW];                   // 13.1 MB
__device__ float  g_lut[NF * NLUT];
__device__ float2 g_tw[320];                                 // e^{-2pi i j/320}

// ---------------------------------------------------------------------------
__device__ __forceinline__ float2 cmulf(float2 a, float2 b) {
    return make_float2(fmaf(a.x, b.x, -(a.y * b.y)), fmaf(a.x, b.y, a.y * b.x));
}

// ---- packed f32x2 helpers ----
__device__ __forceinline__ u64 pack2(float x, float y) {
    u64 r;
    asm("mov.b64 %0, {%1,%2};" : "=l"(r) : "f"(x), "f"(y));
    return r;
}
__device__ __forceinline__ void unpack2(u64 v, float& x, float& y) {
    asm("mov.b64 {%0,%1}, %2;" : "=f"(x), "=f"(y) : "l"(v));
}
__device__ __forceinline__ void fma2(u64& acc, u64 a, u64 b) {
    asm("fma.rn.f32x2 %0, %1, %2, %0;" : "+l"(acc) : "l"(a), "l"(b));
}
__device__ __forceinline__ u64 fma2o(u64 a, u64 b, u64 c) {
    u64 r = c;
    asm("fma.rn.f32x2 %0, %1, %2, %0;" : "+l"(r) : "l"(a), "l"(b));
    return r;
}
__device__ __forceinline__ u64 mul2(u64 a, u64 b) {
    u64 r;
    asm("mul.rn.f32x2 %0, %1, %2;" : "=l"(r) : "l"(a), "l"(b));
    return r;
}
__device__ __forceinline__ u64 add2(u64 a, u64 b) {
    u64 r;
    asm("add.rn.f32x2 %0, %1, %2;" : "=l"(r) : "l"(a), "l"(b));
    return r;
}
__device__ __forceinline__ u64 sub2(u64 a, u64 b) {
    u64 r;
    asm("sub.rn.f32x2 %0, %1, %2;" : "=l"(r) : "l"(a), "l"(b));
    return r;
}

// packed complex mul by scalar twiddle (wr2/wi2 = duplicated lanes).
// table stores w = (c, s) of the FORWARD twiddle; SIGN>0 uses conj(w).
template <int SIGN>
__device__ __forceinline__ void cmulp(u64& cr, u64& ci, u64 ar, u64 ai,
                                      u64 wr2, u64 wi2) {
    if (SIGN < 0) {
        cr = sub2(mul2(ar, wr2), mul2(ai, wi2));
        ci = fma2o(ar, wi2, mul2(ai, wr2));
    } else {
        cr = fma2o(ai, wi2, mul2(ar, wr2));
        ci = sub2(mul2(ai, wr2), mul2(ar, wi2));
    }
}

// One packed radix-4 Stockham stage (two FFTs per lane-pair).
template <int SIGN, int n, int s>
__device__ __forceinline__ void stage4p(const u64* __restrict__ sr,
                                        const u64* __restrict__ si,
                                        u64* __restrict__ dr,
                                        u64* __restrict__ di,
                                        const u64* twr, const u64* twi, int t) {
    const int m = n / 4;
    const int stride = 320 / n;
    int p = t % m, q = t / m;
    u64 a0r = sr[q + s * (p + 0 * m)], a0i = si[q + s * (p + 0 * m)];
    u64 a1r = sr[q + s * (p + 1 * m)], a1i = si[q + s * (p + 1 * m)];
    u64 a2r = sr[q + s * (p + 2 * m)], a2i = si[q + s * (p + 2 * m)];
    u64 a3r = sr[q + s * (p + 3 * m)], a3i = si[q + s * (p + 3 * m)];
    u64 t0r = add2(a0r, a2r), t0i = add2(a0i, a2i);
    u64 t1r = sub2(a0r, a2r), t1i = sub2(a0i, a2i);
    u64 t2r = add2(a1r, a3r), t2i = add2(a1i, a3i);
    u64 t3r = sub2(a1r, a3r), t3i = sub2(a1i, a3i);
    u64 A0r = add2(t0r, t2r), A0i = add2(t0i, t2i);
    u64 A2r = sub2(t0r, t2r), A2i = sub2(t0i, t2i);
    u64 A1r, A1i, A3r, A3i;
    if (SIGN < 0) {
        A1r = add2(t1r, t3i); A1i = sub2(t1i, t3r);
        A3r = sub2(t1r, t3i); A3i = add2(t1i, t3r);
    } else {
        A1r = sub2(t1r, t3i); A1i = add2(t1i, t3r);
        A3r = add2(t1r, t3i); A3i = sub2(t1i, t3r);
    }
    dr[q + s * (4 * p + 0)] = A0r;
    di[q + s * (4 * p + 0)] = A0i;
    u64 cr, ci;
    cmulp<SIGN>(cr, ci, A1r, A1i, twr[p * stride], twi[p * stride]);
    dr[q + s * (4 * p + 1)] = cr; di[q + s * (4 * p + 1)] = ci;
    cmulp<SIGN>(cr, ci, A2r, A2i, twr[2 * p * stride], twi[2 * p * stride]);
    dr[q + s * (4 * p + 2)] = cr; di[q + s * (4 * p + 2)] = ci;
    cmulp<SIGN>(cr, ci, A3r, A3i, twr[3 * p * stride], twi[3 * p * stride]);
    dr[q + s * (4 * p + 3)] = cr; di[q + s * (4 * p + 3)] = ci;
}

// 320-point Stockham FFT on a PACKED PAIR of sequences. Result in X.
// Caller must __syncthreads() between filling X and calling this.
template <int SIGN>
__device__ void fft320p(u64* Xr, u64* Xi, u64* Yr, u64* Yi,
                        const u64* twr, const u64* twi, int t) {
    if (t < 64) {
        int p = t;
        u64 ar[5], ai[5];
#pragma unroll
        for (int j = 0; j < 5; j++) { ar[j] = Xr[p + 64 * j]; ai[j] = Xi[p + 64 * j]; }
#pragma unroll
        for (int k = 0; k < 5; k++) {
            u64 accr = ar[0], acci = ai[0];
#pragma unroll
            for (int j = 1; j < 5; j++) {
                int idx = 64 * ((j * k) % 5);
                u64 pr, pi;
                cmulp<SIGN>(pr, pi, ar[j], ai[j], twr[idx], twi[idx]);
                accr = add2(accr, pr); acci = add2(acci, pi);
            }
            u64 orr, oii;
            cmulp<SIGN>(orr, oii, accr, acci, twr[p * k], twi[p * k]);
            Yr[5 * p + k] = orr; Yi[5 * p + k] = oii;
        }
    }
    __syncthreads();
    stage4p<SIGN, 64, 5>(Yr, Yi, Xr, Xi, twr, twi, t);
    __syncthreads();
    stage4p<SIGN, 16, 20>(Xr, Xi, Yr, Yi, twr, twi, t);
    __syncthreads();
    stage4p<SIGN, 4, 80>(Yr, Yi, Xr, Xi, twr, twi, t);
    __syncthreads();
}

// ---------------------------- init kernels ---------------------------------
__global__ void k_tw() {
    int j = threadIdx.x;
    if (j < 320) {
        double th = -2.0 * 3.14159265358979323846 * (double)j / 320.0;
        g_tw[j] = make_float2((float)cos(th), (float)sin(th));
    }
}

__global__ void k_lut(const float* __restrict__ w, const float* __restrict__ mu,
                      const float* __restrict__ sigma) {
    int f = blockIdx.x;
    float inv2s2 = 1.0f / (2.0f * sigma[0] * sigma[0]);
    for (int t = threadIdx.x; t < NLUT; t += blockDim.x) {
        float x = LUT_MIN + LUT_SPAN * (float)t / (float)(NLUT - 1);
        float acc = 0.0f;
        for (int i = 0; i < 31; i++) {
            float d = x - mu[i];
            acc += w[f * 31 + i] * expf(-d * d * inv2s2);
        }
        g_lut[f * NLUT + t] = acc;
    }
}

__global__ void k_pad(const float* __restrict__ u) {
    int idx = blockIdx.x * blockDim.x + threadIdx.x;
    if (idx >= NB * HP * HP) return;
    int x = idx % HP, y = (idx / HP) % HP, n = idx / (HP * HP);
    int sy = y - 11; sy = (sy < 0) ? -sy : ((sy > 319) ? 638 - sy : sy);
    int sx = x - 11; sx = (sx < 0) ? -sx : ((sx > 319) ? 638 - sx : sx);
    g_upad[idx] = ((const float2*)u)[(n * HH + sy) * WW + sx];
}

// ------------- forward conv (2ch -> 32, 2 features/block) + RBF-LUT --------
// (unchanged from R14: 182us, regs=64, occ 47%)
#define CST 77
__global__ __launch_bounds__(256, 4) void k_conv(const float* __restrict__ ck) {
    __shared__ u64 sIn[42 * CST];                  // packed (re,im)  ~25.9KB
    __shared__ float sLut[2][NLUT];                // 16KB
    __shared__ ulonglong2 sK[121];                 // {wA(re,im), wB(re,im)}
    int nf2 = blockIdx.z, n = nf2 >> 4, fp = nf2 & 15;
    int fA = fp * 2, fB = fA + 1;
    int y0 = blockIdx.y * 32, x0 = blockIdx.x * 64;
    int tid = threadIdx.x;
    for (int i = tid; i < NLUT; i += 256) {
        sLut[0][i] = g_lut[fA * NLUT + i];
        sLut[1][i] = g_lut[fB * NLUT + i];
    }
    const float2* ck2 = (const float2*)ck;
    if (tid < 121) {
        float2 wa = ck2[fA * 121 + tid];
        float2 wb = ck2[fB * 121 + tid];
        sK[tid] = make_ulonglong2(pack2(wa.x, wa.y), pack2(wb.x, wb.y));
    }
    for (int i = tid; i < 42 * CST; i += 256) {
        int ly = i / CST, lx = i % CST;
        int gy = y0 + ly - 5, gx = x0 + lx - 5;
        float2 v = make_float2(0.f, 0.f);
        if (lx < 74 && (unsigned)gy < (unsigned)HP && (unsigned)gx < (unsigned)HP)
            v = g_upad[(n * HP + gy) * HP + gx];
        sIn[i] = pack2(v.x, v.y);
    }
    __syncthreads();
    int ty = tid & 31, txg = (tid >> 5) << 3;
    u64 accA[8], accB[8];
#pragma unroll
    for (int j = 0; j < 8; j++) { accA[j] = 0ull; accB[j] = 0ull; }
#pragma unroll 1
    for (int ky = 0; ky < 11; ky++) {
        u64 v[18];
        const u64* rowp = &sIn[(ty + ky) * CST + txg];
#pragma unroll
        for (int p = 0; p < 18; p++) v[p] = rowp[p];
#pragma unroll
        for (int kx = 0; kx < 11; kx++) {
            ulonglong2 wv = sK[ky * 11 + kx];
#pragma unroll
            for (int j = 0; j < 8; j++) {
                fma2(accA[j], v[kx + j], wv.x);
                fma2(accB[j], v[kx + j], wv.y);
            }
        }
    }
    __syncthreads();
    float* sOut = (float*)sIn;
#pragma unroll
    for (int j = 0; j < 8; j++) {
        float lo, hi;
        unpack2(accA[j], lo, hi);
        float a = lo + hi;
        float tpos = (a - LUT_MIN) * LUT_SCALE;
        tpos = fminf(fmaxf(tpos, 0.f), (float)(NLUT - 1) - 0.001f);
        int ii = (int)tpos;
        float fr = tpos - (float)ii;
        sOut[ty * 65 + txg + j] = sLut[0][ii] + fr * (sLut[0][ii + 1] - sLut[0][ii]);
        unpack2(accB[j], lo, hi);
        a = lo + hi;
        tpos = (a - LUT_MIN) * LUT_SCALE;
        tpos = fminf(fmaxf(tpos, 0.f), (float)(NLUT - 1) - 0.001f);
        ii = (int)tpos;
        fr = tpos - (float)ii;
        sOut[2080 + ty * 65 + txg + j] = sLut[1][ii] + fr * (sLut[1][ii + 1] - sLut[1][ii]);
    }
    __syncthreads();
    for (int i = tid; i < 32 * 64; i += 256) {
        int row = i >> 6, col = i & 63;
        int y = y0 + row, x = x0 + col;
        if (y < HP && x < HP) {
            g_fuk[((n * NF + fA) * HP + y) * HP + x] = sOut[row * 65 + col];
            g_fuk[((n * NF + fB) * HP + y) * HP + x] = sOut[2080 + row * 65 + col];
        }
    }
}

// --------------------- FFT passes (packed row/col pairs) -------------------
// Row passes: block = 4 packed pairs = 8 rows. 2400 blocks.
__global__ __launch_bounds__(320, 3) void k_fft_row_fwd(
        const float* __restrict__ u, const float* __restrict__ cs) {
    __shared__ u64 bR[4][2][320], bI[4][2][320];   // 40KB
    __shared__ u64 sTwR[320], sTwI[320];           // 5KB
    int tid = threadIdx.x;
    {
        float2 tw = g_tw[tid];
        sTwR[tid] = pack2(tw.x, tw.x);
        sTwI[tid] = pack2(tw.y, tw.y);
    }
    int g = tid / 80, t = tid % 80;
    int pairIdx = blockIdx.x * 4 + g;          // [0, 9600)
    int nc = pairIdx / 160, rp = pairIdx % 160;
    int r0 = 2 * rp, r1 = r0 + 1;
    int n = nc / NCOIL;
    const float2* up0 = (const float2*)u + (n * HH + r0) * WW;
    const float2* up1 = (const float2*)u + (n * HH + r1) * WW;
    const float2* cp0 = (const float2*)cs + (nc * HH + r0) * WW;
    const float2* cp1 = (const float2*)cs + (nc * HH + r1) * WW;
    u64* Xr = &bR[g][0][0]; u64* Yr = &bR[g][1][0];
    u64* Xi = &bI[g][0][0]; u64* Yi = &bI[g][1][0];
    for (int x = t; x < 320; x += 80) {
        float2 qa = cmulf(up0[x], cp0[x]);
        float2 qb = cmulf(up1[x], cp1[x]);
        float sA = ((r0 + x) & 1) ? -1.f : 1.f;   // sB = -sA (r1 = r0+1)
        Xr[x] = pack2(sA * qa.x, -sA * qb.x);
        Xi[x] = pack2(sA * qa.y, -sA * qb.y);
    }
    __syncthreads();
    fft320p<-1>(Xr, Xi, Yr, Yi, sTwR, sTwI, t);
    float2* d0 = g_work + nc * (HH * WW) + r0 * WW;
    float2* d1 = g_work + nc * (HH * WW) + r1 * WW;
    const float sc = 1.f / 320.f;
    for (int x = t; x < 320; x += 80) {
        float ra, rb, ia, ib;
        unpack2(Xr[x], ra, rb);
        unpack2(Xi[x], ia, ib);
        d0[x] = make_float2(ra * sc, ia * sc);
        d1[x] = make_float2(rb * sc, ib * sc);
    }
}

// Col fwd: block = 8 columns (4 pairs). 2400 blocks. S = m*(Q - D*f).
__global__ __launch_bounds__(320, 3) void k_fft_col_fwd(
        const float* __restrict__ fdat, const float* __restrict__ mask) {
    __shared__ u64 bR[4][2][320], bI[4][2][320];
    __shared__ u64 sTwR[320], sTwI[320];
    int tid = threadIdx.x;
    {
        float2 tw = g_tw[tid];
        sTwR[tid] = pack2(tw.x, tw.x);
        sTwI[tid] = pack2(tw.y, tw.y);
    }
    int blk = blockIdx.x;
    int nc = blk / 40, cb = (blk % 40) * 8;
    int n = nc / NCOIL;
    float2* base = g_work + nc * (HH * WW);
    for (int i = tid; i < 1280; i += 320) {
        int row = i >> 2, pr = i & 3;
        float4 q = *(const float4*)(base + row * WW + cb + 2 * pr);
        bR[pr][0][row] = pack2(q.x, q.z);
        bI[pr][0][row] = pack2(q.y, q.w);
    }
    __syncthreads();
    int g = tid / 80, t = tid % 80;
    fft320p<-1>(&bR[g][0][0], &bI[g][0][0], &bR[g][1][0], &bI[g][1][0],
                sTwR, sTwI, t);
    const float2* f2 = (const float2*)fdat + nc * (HH * WW);
    const float* mrow = mask + n * (HH * WW);
    for (int i = tid; i < 1280; i += 320) {
        int row = i >> 2, pr = i & 3;
        int c0 = cb + 2 * pr;
        float mA = mrow[row * WW + c0], mB = mrow[row * WW + c0 + 1];
        float4 fv = *(const float4*)(f2 + row * WW + c0);
        float sA = ((row + c0) & 1) ? -1.f : 1.f;   // sB = -sA
        float qrA, qrB, qiA, qiB;
        unpack2(bR[pr][0][row], qrA, qrB);
        unpack2(bI[pr][0][row], qiA, qiB);
        float4 o;
        o.x = mA * (qrA - sA * fv.x);
        o.y = mA * (qiA - sA * fv.y);
        o.z = mB * (qrB + sA * fv.z);
        o.w = mB * (qiB + sA * fv.w);
        *(float4*)(base + row * WW + c0) = o;
    }
}

__global__ __launch_bounds__(320, 3) void k_fft_row_inv() {
    __shared__ u64 bR[4][2][320], bI[4][2][320];
    __shared__ u64 sTwR[320], sTwI[320];
    int tid = threadIdx.x;
    {
        float2 tw = g_tw[tid];
        sTwR[tid] = pack2(tw.x, tw.x);
        sTwI[tid] = pack2(tw.y, tw.y);
    }
    int g = tid / 80, t = tid % 80;
    int pairIdx = blockIdx.x * 4 + g;
    int nc = pairIdx / 160, rp = pairIdx % 160;
    int r0 = 2 * rp, r1 = r0 + 1;
    float2* p0 = g_work + nc * (HH * WW) + r0 * WW;
    float2* p1 = g_work + nc * (HH * WW) + r1 * WW;
    u64* Xr = &bR[g][0][0]; u64* Yr = &bR[g][1][0];
    u64* Xi = &bI[g][0][0]; u64* Yi = &bI[g][1][0];
    for (int x = t; x < 320; x += 80) {
        float2 a = p0[x], b = p1[x];
        Xr[x] = pack2(a.x, b.x);
        Xi[x] = pack2(a.y, b.y);
    }
    __syncthreads();
    fft320p<1>(Xr, Xi, Yr, Yi, sTwR, sTwI, t);
    const float sc = 1.f / 320.f;
    for (int x = t; x < 320; x += 80) {
        float ra, rb, ia, ib;
        unpack2(Xr[x], ra, rb);
        unpack2(Xi[x], ia, ib);
        p0[x] = make_float2(ra * sc, ia * sc);
        p1[x] = make_float2(rb * sc, ib * sc);
    }
}

// Col inv + D * v * conj(cs). 2400 blocks.
__global__ __launch_bounds__(320, 3) void k_fft_col_inv(
        const float* __restrict__ cs) {
    __shared__ u64 bR[4][2][320], bI[4][2][320];
    __shared__ u64 sTwR[320], sTwI[320];
    int tid = threadIdx.x;
    {
        float2 tw = g_tw[tid];
        sTwR[tid] = pack2(tw.x, tw.x);
        sTwI[tid] = pack2(tw.y, tw.y);
    }
    int blk = blockIdx.x;
    int nc = blk / 40, cb = (blk % 40) * 8;
    float2* base = g_work + nc * (HH * WW);
    for (int i = tid; i < 1280; i += 320) {
        int row = i >> 2, pr = i & 3;
        float4 q = *(const float4*)(base + row * WW + cb + 2 * pr);
        bR[pr][0][row] = pack2(q.x, q.z);
        bI[pr][0][row] = pack2(q.y, q.w);
    }
    __syncthreads();
    int g = tid / 80, t = tid % 80;
    fft320p<1>(&bR[g][0][0], &bI[g][0][0], &bR[g][1][0], &bI[g][1][0],
               sTwR, sTwI, t);
    const float2* c2 = (const float2*)cs + nc * (HH * WW);
    for (int i = tid; i < 1280; i += 320) {
        int row = i >> 2, pr = i & 3;
        int c0 = cb + 2 * pr;
        float4 cv = *(const float4*)(c2 + row * WW + c0);
        float sA = ((row + c0) & 1) ? -1.f : 1.f;   // sB = -sA
        float vrA, vrB, viA, viB;
        unpack2(bR[pr][0][row], vrA, vrB);
        unpack2(bI[pr][0][row], viA, viB);
        float4 o;
        o.x = sA * (vrA * cv.x + viA * cv.y);
        o.y = sA * (viA * cv.x - vrA * cv.y);
        o.z = -sA * (vrB * cv.z + viB * cv.w);
        o.w = -sA * (viB * cv.z - vrB * cv.w);
        *(float4*)(base + row * WW + c0) = o;
    }
}

// ----------------- adjoint conv partials (feature-paired) ------------------
#define FST 77
__global__ __launch_bounds__(128) void k_adj(const float* __restrict__ ck) {
    __shared__ u64 sT[26 * FST];                     // 16KB
    __shared__ ulonglong2 sK[121];
    int zz = blockIdx.z, n = zz >> 2, chunk = zz & 3;
    int y0 = blockIdx.y * 16, x0 = blockIdx.x * 64;
    int tid = threadIdx.x;
    int ty = tid & 15, txg = (tid >> 4) << 3;
    u64 accre[8], accim[8];
#pragma unroll
    for (int j = 0; j < 8; j++) { accre[j] = 0ull; accim[j] = 0ull; }
    const float2* ck2 = (const float2*)ck;
#pragma unroll 1
    for (int p = 0; p < 4; p++) {
        int fA = (chunk * 4 + p) * 2, fB = fA + 1;
        __syncthreads();
        const float* baseA = &g_fuk[(n * NF + fA) * HP * HP];
        const float* baseB = &g_fuk[(n * NF + fB) * HP * HP];
        for (int i = tid; i < 26 * FST; i += 128) {
            int ly = i / FST, lx = i % FST;
            float vA = 0.f, vB = 0.f;
            if (lx < 74) {
                int off = (y0 + 6 + ly) * HP + (x0 + 6 + lx);
                vA = baseA[off];
                vB = baseB[off];
            }
            sT[i] = pack2(vA, vB);
        }
        if (tid < 121) {
            float2 wA = ck2[fA * 121 + 120 - tid];
            float2 wB = ck2[fB * 121 + 120 - tid];
            sK[tid] = make_ulonglong2(pack2(wA.x, wB.x), pack2(wA.y, wB.y));
        }
        __syncthreads();
#pragma unroll 1
        for (int ky = 0; ky < 11; ky++) {
            u64 v[18];
            const u64* rowp = &sT[(ty + ky) * FST + txg];
#pragma unroll
            for (int q = 0; q < 18; q++) v[q] = rowp[q];
#pragma unroll
            for (int kx = 0; kx < 11; kx++) {
                ulonglong2 wv = sK[ky * 11 + kx];
#pragma unroll
                for (int j = 0; j < 8; j++) {
                    fma2(accre[j], v[kx + j], wv.x);
                    fma2(accim[j], v[kx + j], wv.y);
                }
            }
        }
    }
    int y = y0 + ty;
    float2* dst = &g_adj[((chunk * NB + n) * HH + y) * WW + x0 + txg];
#pragma unroll
    for (int j = 0; j < 8; j++) {
        float a, b, c, d;
        unpack2(accre[j], a, b);
        unpack2(accim[j], c, d);
        dst[j] = make_float2(a + b, c + d);
    }
}

// ------------- final combine: u - Ru - Du ----------------------------------
__global__ void k_combine(const float* __restrict__ u,
                          const float* __restrict__ lamb,
                          float2* __restrict__ out) {
    int idx = blockIdx.x * blockDim.x + threadIdx.x;
    if (idx >= NB * HH * WW) return;
    int pix = idx % (HH * WW), n = idx / (HH * WW);
    float lam = lamb[0];
    float2 ru = make_float2(0.f, 0.f);
#pragma unroll
    for (int c = 0; c < 4; c++) {
        float2 v = g_adj[(c * NB + n) * (HH * WW) + pix];
        ru.x += v.x; ru.y += v.y;
    }
    float2 du = make_float2(0.f, 0.f);
#pragma unroll 1
    for (int c = 0; c < NCOIL; c++) {
        float2 v = g_work[(n * NCOIL + c) * (HH * WW) + pix];
        du.x += v.x; du.y += v.y;
    }
    float2 uu = ((const float2*)u)[idx];
    float2 o;
    o.x = uu.x - ru.x * (1.f / 32.f) - lam * du.x;
    o.y = uu.y - ru.y * (1.f / 32.f) - lam * du.y;
    out[idx] = o;
}

// ---------------------------------------------------------------------------
extern "C" void kernel_launch(void* const* d_in, const int* in_sizes, int n_in,
                              void* d_out, int out_size) {
    const float* u_t   = (const float*)d_in[0];
    const float* fdat  = (const float*)d_in[1];
    const float* cs    = (const float*)d_in[2];
    const float* mask  = (const float*)d_in[3];
    const float* ck    = (const float*)d_in[4];
    const float* w     = (const float*)d_in[5];
    const float* mu    = (const float*)d_in[6];
    const float* sigma = (const float*)d_in[7];
    const float* lamb  = (const float*)d_in[8];
    float2* out = (float2*)d_out;

    cudaFuncSetAttribute(k_conv,
        cudaFuncAttributePreferredSharedMemoryCarveout, 100);

    k_tw<<<1, 320>>>();
    k_lut<<<NF, 256>>>(w, mu, sigma);
    k_pad<<<(NB * HP * HP + 255) / 256, 256>>>(u_t);
    k_conv<<<dim3(6, 11, NB * 16), 256>>>(ck);

    k_fft_row_fwd<<<2400, 320>>>(u_t, cs);
    k_fft_col_fwd<<<2400, 320>>>(fdat, mask);
    k_fft_row_inv<<<2400, 320>>>();
    k_fft_col_inv<<<2400, 320>>>(cs);

    k_adj<<<dim3(5, 20, NB * 4), 128>>>(ck);
    k_combine<<<(NB * HH * WW + 255) / 256, 256>>>(u_t, lamb, out);
}

// round 17
// speedup vs baseline: 1.1178x; 1.0123x over previous
#include <cuda_runtime.h>
#include <math.h>

#define NB 4
#define NCOIL 15
#define HH 320
#define WW 320
#define NF 32
#define KS 11
#define HP 342          // 320 + 2*11
#define NLUT 2048
#define LUT_MIN (-1.6f)
#define LUT_SPAN (3.2f)
#define LUT_SCALE ((float)(NLUT - 1) / LUT_SPAN)

typedef unsigned long long u64;

// -------- scratch (device globals; no runtime allocation allowed) ----------
__device__ float2 g_upad[NB * HP * HP];                      // ~3.7 MB
__device__ float  g_fuk[NB * NF * HP * HP];                  // ~60 MB
__device__ __align__(16) float2 g_work[NB * NCOIL * HH * WW];// ~49 MB
__device__ float2 g_adj[4 * NB * HH * WW];                   // 13.1 MB
__device__ float  g_lut[NF * NLUT];
__device__ float2 g_tw[320];                                 // e^{-2pi i j/320}

// ---------------------------------------------------------------------------
__device__ __forceinline__ float2 cmulf(float2 a, float2 b) {
    return make_float2(fmaf(a.x, b.x, -(a.y * b.y)), fmaf(a.x, b.y, a.y * b.x));
}

// ---- packed f32x2 helpers ----
__device__ __forceinline__ u64 pack2(float x, float y) {
    u64 r;
    asm("mov.b64 %0, {%1,%2};" : "=l"(r) : "f"(x), "f"(y));
    return r;
}
__device__ __forceinline__ void unpack2(u64 v, float& x, float& y) {
    asm("mov.b64 {%0,%1}, %2;" : "=f"(x), "=f"(y) : "l"(v));
}
__device__ __forceinline__ void fma2(u64& acc, u64 a, u64 b) {
    asm("fma.rn.f32x2 %0, %1, %2, %0;" : "+l"(acc) : "l"(a), "l"(b));
}
__device__ __forceinline__ u64 fma2o(u64 a, u64 b, u64 c) {
    u64 r = c;
    asm("fma.rn.f32x2 %0, %1, %2, %0;" : "+l"(r) : "l"(a), "l"(b));
    return r;
}
__device__ __forceinline__ u64 mul2(u64 a, u64 b) {
    u64 r;
    asm("mul.rn.f32x2 %0, %1, %2;" : "=l"(r) : "l"(a), "l"(b));
    return r;
}
__device__ __forceinline__ u64 add2(u64 a, u64 b) {
    u64 r;
    asm("add.rn.f32x2 %0, %1, %2;" : "=l"(r) : "l"(a), "l"(b));
    return r;
}
__device__ __forceinline__ u64 sub2(u64 a, u64 b) {
    u64 r;
    asm("sub.rn.f32x2 %0, %1, %2;" : "=l"(r) : "l"(a), "l"(b));
    return r;
}

// packed complex mul by scalar twiddle (wr2/wi2 = duplicated lanes).
// table stores w = (c, s) of the FORWARD twiddle; SIGN>0 uses conj(w).
template <int SIGN>
__device__ __forceinline__ void cmulp(u64& cr, u64& ci, u64 ar, u64 ai,
                                      u64 wr2, u64 wi2) {
    if (SIGN < 0) {
        cr = sub2(mul2(ar, wr2), mul2(ai, wi2));
        ci = fma2o(ar, wi2, mul2(ai, wr2));
    } else {
        cr = fma2o(ai, wi2, mul2(ar, wr2));
        ci = sub2(mul2(ai, wr2), mul2(ar, wi2));
    }
}

// One packed radix-4 Stockham stage (two FFTs per lane-pair).
template <int SIGN, int n, int s>
__device__ __forceinline__ void stage4p(const u64* __restrict__ sr,
                                        const u64* __restrict__ si,
                                        u64* __restrict__ dr,
                                        u64* __restrict__ di,
                                        const u64* twr, const u64* twi, int t) {
    const int m = n / 4;
    const int stride = 320 / n;
    int p = t % m, q = t / m;
    u64 a0r = sr[q + s * (p + 0 * m)], a0i = si[q + s * (p + 0 * m)];
    u64 a1r = sr[q + s * (p + 1 * m)], a1i = si[q + s * (p + 1 * m)];
    u64 a2r = sr[q + s * (p + 2 * m)], a2i = si[q + s * (p + 2 * m)];
    u64 a3r = sr[q + s * (p + 3 * m)], a3i = si[q + s * (p + 3 * m)];
    u64 t0r = add2(a0r, a2r), t0i = add2(a0i, a2i);
    u64 t1r = sub2(a0r, a2r), t1i = sub2(a0i, a2i);
    u64 t2r = add2(a1r, a3r), t2i = add2(a1i, a3i);
    u64 t3r = sub2(a1r, a3r), t3i = sub2(a1i, a3i);
    u64 A0r = add2(t0r, t2r), A0i = add2(t0i, t2i);
    u64 A2r = sub2(t0r, t2r), A2i = sub2(t0i, t2i);
    u64 A1r, A1i, A3r, A3i;
    if (SIGN < 0) {
        A1r = add2(t1r, t3i); A1i = sub2(t1i, t3r);
        A3r = sub2(t1r, t3i); A3i = add2(t1i, t3r);
    } else {
        A1r = sub2(t1r, t3i); A1i = add2(t1i, t3r);
        A3r = add2(t1r, t3i); A3i = sub2(t1i, t3r);
    }
    dr[q + s * (4 * p + 0)] = A0r;
    di[q + s * (4 * p + 0)] = A0i;
    u64 cr, ci;
    cmulp<SIGN>(cr, ci, A1r, A1i, twr[p * stride], twi[p * stride]);
    dr[q + s * (4 * p + 1)] = cr; di[q + s * (4 * p + 1)] = ci;
    cmulp<SIGN>(cr, ci, A2r, A2i, twr[2 * p * stride], twi[2 * p * stride]);
    dr[q + s * (4 * p + 2)] = cr; di[q + s * (4 * p + 2)] = ci;
    cmulp<SIGN>(cr, ci, A3r, A3i, twr[3 * p * stride], twi[3 * p * stride]);
    dr[q + s * (4 * p + 3)] = cr; di[q + s * (4 * p + 3)] = ci;
}

// 320-point Stockham FFT on a PACKED PAIR of sequences. Result in X.
// Caller must __syncthreads() between filling X and calling this.
template <int SIGN>
__device__ void fft320p(u64* Xr, u64* Xi, u64* Yr, u64* Yi,
                        const u64* twr, const u64* twi, int t) {
    if (t < 64) {
        int p = t;
        u64 ar[5], ai[5];
#pragma unroll
        for (int j = 0; j < 5; j++) { ar[j] = Xr[p + 64 * j]; ai[j] = Xi[p + 64 * j]; }
#pragma unroll
        for (int k = 0; k < 5; k++) {
            u64 accr = ar[0], acci = ai[0];
#pragma unroll
            for (int j = 1; j < 5; j++) {
                int idx = 64 * ((j * k) % 5);
                u64 pr, pi;
                cmulp<SIGN>(pr, pi, ar[j], ai[j], twr[idx], twi[idx]);
                accr = add2(accr, pr); acci = add2(acci, pi);
            }
            u64 orr, oii;
            cmulp<SIGN>(orr, oii, accr, acci, twr[p * k], twi[p * k]);
            Yr[5 * p + k] = orr; Yi[5 * p + k] = oii;
        }
    }
    __syncthreads();
    stage4p<SIGN, 64, 5>(Yr, Yi, Xr, Xi, twr, twi, t);
    __syncthreads();
    stage4p<SIGN, 16, 20>(Xr, Xi, Yr, Yi, twr, twi, t);
    __syncthreads();
    stage4p<SIGN, 4, 80>(Yr, Yi, Xr, Xi, twr, twi, t);
    __syncthreads();
}

// ---------------------------- init kernels ---------------------------------
__global__ void k_tw() {
    int j = threadIdx.x;
    if (j < 320) {
        double th = -2.0 * 3.14159265358979323846 * (double)j / 320.0;
        g_tw[j] = make_float2((float)cos(th), (float)sin(th));
    }
}

__global__ void k_lut(const float* __restrict__ w, const float* __restrict__ mu,
                      const float* __restrict__ sigma) {
    int f = blockIdx.x;
    float inv2s2 = 1.0f / (2.0f * sigma[0] * sigma[0]);
    for (int t = threadIdx.x; t < NLUT; t += blockDim.x) {
        float x = LUT_MIN + LUT_SPAN * (float)t / (float)(NLUT - 1);
        float acc = 0.0f;
        for (int i = 0; i < 31; i++) {
            float d = x - mu[i];
            acc += w[f * 31 + i] * expf(-d * d * inv2s2);
        }
        g_lut[f * NLUT + t] = acc;
    }
}

__global__ void k_pad(const float* __restrict__ u) {
    int idx = blockIdx.x * blockDim.x + threadIdx.x;
    if (idx >= NB * HP * HP) return;
    int x = idx % HP, y = (idx / HP) % HP, n = idx / (HP * HP);
    int sy = y - 11; sy = (sy < 0) ? -sy : ((sy > 319) ? 638 - sy : sy);
    int sx = x - 11; sx = (sx < 0) ? -sx : ((sx > 319) ? 638 - sx : sx);
    g_upad[idx] = ((const float2*)u)[(n * HH + sy) * WW + sx];
}

// ------------- forward conv (2ch -> 32, 2 features/block) + RBF-LUT --------
// (unchanged: 182us, regs=64, occ 47%)
#define CST 77
__global__ __launch_bounds__(256, 4) void k_conv(const float* __restrict__ ck) {
    __shared__ u64 sIn[42 * CST];                  // packed (re,im)  ~25.9KB
    __shared__ float sLut[2][NLUT];                // 16KB
    __shared__ ulonglong2 sK[121];                 // {wA(re,im), wB(re,im)}
    int nf2 = blockIdx.z, n = nf2 >> 4, fp = nf2 & 15;
    int fA = fp * 2, fB = fA + 1;
    int y0 = blockIdx.y * 32, x0 = blockIdx.x * 64;
    int tid = threadIdx.x;
    for (int i = tid; i < NLUT; i += 256) {
        sLut[0][i] = g_lut[fA * NLUT + i];
        sLut[1][i] = g_lut[fB * NLUT + i];
    }
    const float2* ck2 = (const float2*)ck;
    if (tid < 121) {
        float2 wa = ck2[fA * 121 + tid];
        float2 wb = ck2[fB * 121 + tid];
        sK[tid] = make_ulonglong2(pack2(wa.x, wa.y), pack2(wb.x, wb.y));
    }
    for (int i = tid; i < 42 * CST; i += 256) {
        int ly = i / CST, lx = i % CST;
        int gy = y0 + ly - 5, gx = x0 + lx - 5;
        float2 v = make_float2(0.f, 0.f);
        if (lx < 74 && (unsigned)gy < (unsigned)HP && (unsigned)gx < (unsigned)HP)
            v = g_upad[(n * HP + gy) * HP + gx];
        sIn[i] = pack2(v.x, v.y);
    }
    __syncthreads();
    int ty = tid & 31, txg = (tid >> 5) << 3;
    u64 accA[8], accB[8];
#pragma unroll
    for (int j = 0; j < 8; j++) { accA[j] = 0ull; accB[j] = 0ull; }
#pragma unroll 1
    for (int ky = 0; ky < 11; ky++) {
        u64 v[18];
        const u64* rowp = &sIn[(ty + ky) * CST + txg];
#pragma unroll
        for (int p = 0; p < 18; p++) v[p] = rowp[p];
#pragma unroll
        for (int kx = 0; kx < 11; kx++) {
            ulonglong2 wv = sK[ky * 11 + kx];
#pragma unroll
            for (int j = 0; j < 8; j++) {
                fma2(accA[j], v[kx + j], wv.x);
                fma2(accB[j], v[kx + j], wv.y);
            }
        }
    }
    __syncthreads();
    float* sOut = (float*)sIn;
#pragma unroll
    for (int j = 0; j < 8; j++) {
        float lo, hi;
        unpack2(accA[j], lo, hi);
        float a = lo + hi;
        float tpos = (a - LUT_MIN) * LUT_SCALE;
        tpos = fminf(fmaxf(tpos, 0.f), (float)(NLUT - 1) - 0.001f);
        int ii = (int)tpos;
        float fr = tpos - (float)ii;
        sOut[ty * 65 + txg + j] = sLut[0][ii] + fr * (sLut[0][ii + 1] - sLut[0][ii]);
        unpack2(accB[j], lo, hi);
        a = lo + hi;
        tpos = (a - LUT_MIN) * LUT_SCALE;
        tpos = fminf(fmaxf(tpos, 0.f), (float)(NLUT - 1) - 0.001f);
        ii = (int)tpos;
        fr = tpos - (float)ii;
        sOut[2080 + ty * 65 + txg + j] = sLut[1][ii] + fr * (sLut[1][ii + 1] - sLut[1][ii]);
    }
    __syncthreads();
    for (int i = tid; i < 32 * 64; i += 256) {
        int row = i >> 6, col = i & 63;
        int y = y0 + row, x = x0 + col;
        if (y < HP && x < HP) {
            g_fuk[((n * NF + fA) * HP + y) * HP + x] = sOut[row * 65 + col];
            g_fuk[((n * NF + fB) * HP + y) * HP + x] = sOut[2080 + row * 65 + col];
        }
    }
}

// --------------------- FFT passes (packed, 3 passes) -----------------------
// Pass 1: rows forward. q = D*(u*cs), row-FFT, scale 1/320.  2400 blocks.
__global__ __launch_bounds__(320, 3) void k_fft_row_fwd(
        const float* __restrict__ u, const float* __restrict__ cs) {
    __shared__ u64 bR[4][2][320], bI[4][2][320];   // 40KB
    __shared__ u64 sTwR[320], sTwI[320];           // 5KB
    int tid = threadIdx.x;
    {
        float2 tw = g_tw[tid];
        sTwR[tid] = pack2(tw.x, tw.x);
        sTwI[tid] = pack2(tw.y, tw.y);
    }
    int g = tid / 80, t = tid % 80;
    int pairIdx = blockIdx.x * 4 + g;          // [0, 9600)
    int nc = pairIdx / 160, rp = pairIdx % 160;
    int r0 = 2 * rp, r1 = r0 + 1;
    int n = nc / NCOIL;
    const float2* up0 = (const float2*)u + (n * HH + r0) * WW;
    const float2* up1 = (const float2*)u + (n * HH + r1) * WW;
    const float2* cp0 = (const float2*)cs + (nc * HH + r0) * WW;
    const float2* cp1 = (const float2*)cs + (nc * HH + r1) * WW;
    u64* Xr = &bR[g][0][0]; u64* Yr = &bR[g][1][0];
    u64* Xi = &bI[g][0][0]; u64* Yi = &bI[g][1][0];
    for (int x = t; x < 320; x += 80) {
        float2 qa = cmulf(up0[x], cp0[x]);
        float2 qb = cmulf(up1[x], cp1[x]);
        float sA = ((r0 + x) & 1) ? -1.f : 1.f;   // sB = -sA (r1 = r0+1)
        Xr[x] = pack2(sA * qa.x, -sA * qb.x);
        Xi[x] = pack2(sA * qa.y, -sA * qb.y);
    }
    __syncthreads();
    fft320p<-1>(Xr, Xi, Yr, Yi, sTwR, sTwI, t);
    float2* d0 = g_work + nc * (HH * WW) + r0 * WW;
    float2* d1 = g_work + nc * (HH * WW) + r1 * WW;
    const float sc = 1.f / 320.f;
    for (int x = t; x < 320; x += 80) {
        float ra, rb, ia, ib;
        unpack2(Xr[x], ra, rb);
        unpack2(Xi[x], ia, ib);
        d0[x] = make_float2(ra * sc, ia * sc);
        d1[x] = make_float2(rb * sc, ib * sc);
    }
}

// Pass 2 (FUSED): col fwd FFT -> S = m*(Q - D*f) in smem -> col inv FFT.
// One global round-trip instead of two. 2400 blocks.
__global__ __launch_bounds__(320, 3) void k_fft_col_mid(
        const float* __restrict__ fdat, const float* __restrict__ mask) {
    __shared__ u64 bR[4][2][320], bI[4][2][320];
    __shared__ u64 sTwR[320], sTwI[320];
    int tid = threadIdx.x;
    {
        float2 tw = g_tw[tid];
        sTwR[tid] = pack2(tw.x, tw.x);
        sTwI[tid] = pack2(tw.y, tw.y);
    }
    int blk = blockIdx.x;
    int nc = blk / 40, cb = (blk % 40) * 8;
    int n = nc / NCOIL;
    float2* base = g_work + nc * (HH * WW);
    for (int i = tid; i < 1280; i += 320) {
        int row = i >> 2, pr = i & 3;
        float4 q = *(const float4*)(base + row * WW + cb + 2 * pr);
        bR[pr][0][row] = pack2(q.x, q.z);
        bI[pr][0][row] = pack2(q.y, q.w);
    }
    __syncthreads();
    int g = tid / 80, t = tid % 80;
    fft320p<-1>(&bR[g][0][0], &bI[g][0][0], &bR[g][1][0], &bI[g][1][0],
                sTwR, sTwI, t);
    // epilogue in smem: S = m * (Q - D*f)
    const float2* f2 = (const float2*)fdat + nc * (HH * WW);
    const float* mrow = mask + n * (HH * WW);
    for (int i = tid; i < 1280; i += 320) {
        int row = i >> 2, pr = i & 3;
        int c0 = cb + 2 * pr;
        float mA = mrow[row * WW + c0], mB = mrow[row * WW + c0 + 1];
        float4 fv = *(const float4*)(f2 + row * WW + c0);
        float sA = ((row + c0) & 1) ? -1.f : 1.f;   // sB = -sA
        float qrA, qrB, qiA, qiB;
        unpack2(bR[pr][0][row], qrA, qrB);
        unpack2(bI[pr][0][row], qiA, qiB);
        bR[pr][0][row] = pack2(mA * (qrA - sA * fv.x), mB * (qrB + sA * fv.z));
        bI[pr][0][row] = pack2(mA * (qiA - sA * fv.y), mB * (qiB + sA * fv.w));
    }
    __syncthreads();
    // inverse column FFT on the same data (ifft2 order-free)
    fft320p<1>(&bR[g][0][0], &bI[g][0][0], &bR[g][1][0], &bI[g][1][0],
               sTwR, sTwI, t);
    for (int i = tid; i < 1280; i += 320) {
        int row = i >> 2, pr = i & 3;
        int c0 = cb + 2 * pr;
        float vrA, vrB, viA, viB;
        unpack2(bR[pr][0][row], vrA, vrB);
        unpack2(bI[pr][0][row], viA, viB);
        float4 o = make_float4(vrA, viA, vrB, viB);
        *(float4*)(base + row * WW + c0) = o;
    }
}

// Pass 3: rows inverse + scale 1/320 + D * v * conj(cs). 2400 blocks.
__global__ __launch_bounds__(320, 3) void k_fft_row_inv(
        const float* __restrict__ cs) {
    __shared__ u64 bR[4][2][320], bI[4][2][320];
    __shared__ u64 sTwR[320], sTwI[320];
    int tid = threadIdx.x;
    {
        float2 tw = g_tw[tid];
        sTwR[tid] = pack2(tw.x, tw.x);
        sTwI[tid] = pack2(tw.y, tw.y);
    }
    int g = tid / 80, t = tid % 80;
    int pairIdx = blockIdx.x * 4 + g;
    int nc = pairIdx / 160, rp = pairIdx % 160;
    int r0 = 2 * rp, r1 = r0 + 1;
    float2* p0 = g_work + nc * (HH * WW) + r0 * WW;
    float2* p1 = g_work + nc * (HH * WW) + r1 * WW;
    const float2* cp0 = (const float2*)cs + (nc * HH + r0) * WW;
    const float2* cp1 = (const float2*)cs + (nc * HH + r1) * WW;
    u64* Xr = &bR[g][0][0]; u64* Yr = &bR[g][1][0];
    u64* Xi = &bI[g][0][0]; u64* Yi = &bI[g][1][0];
    for (int x = t; x < 320; x += 80) {
        float2 a = p0[x], b = p1[x];
        Xr[x] = pack2(a.x, b.x);
        Xi[x] = pack2(a.y, b.y);
    }
    __syncthreads();
    fft320p<1>(Xr, Xi, Yr, Yi, sTwR, sTwI, t);
    const float sc = 1.f / 320.f;
    for (int x = t; x < 320; x += 80) {
        float ra, rb, ia, ib;
        unpack2(Xr[x], ra, rb);
        unpack2(Xi[x], ia, ib);
        float2 c0 = cp0[x], c1 = cp1[x];
        float sA = ((r0 + x) & 1) ? -1.f : 1.f;   // sB = -sA
        float2 o0, o1;
        o0.x = sA * sc * (ra * c0.x + ia * c0.y);
        o0.y = sA * sc * (ia * c0.x - ra * c0.y);
        o1.x = -sA * sc * (rb * c1.x + ib * c1.y);
        o1.y = -sA * sc * (ib * c1.x - rb * c1.y);
        p0[x] = o0;
        p1[x] = o1;
    }
}

// ----------------- adjoint conv partials (feature-paired) ------------------
#define FST 77
__global__ __launch_bounds__(128) void k_adj(const float* __restrict__ ck) {
    __shared__ u64 sT[26 * FST];                     // 16KB
    __shared__ ulonglong2 sK[121];
    int zz = blockIdx.z, n = zz >> 2, chunk = zz & 3;
    int y0 = blockIdx.y * 16, x0 = blockIdx.x * 64;
    int tid = threadIdx.x;
    int ty = tid & 15, txg = (tid >> 4) << 3;
    u64 accre[8], accim[8];
#pragma unroll
    for (int j = 0; j < 8; j++) { accre[j] = 0ull; accim[j] = 0ull; }
    const float2* ck2 = (const float2*)ck;
#pragma unroll 1
    for (int p = 0; p < 4; p++) {
        int fA = (chunk * 4 + p) * 2, fB = fA + 1;
        __syncthreads();
        const float* baseA = &g_fuk[(n * NF + fA) * HP * HP];
        const float* baseB = &g_fuk[(n * NF + fB) * HP * HP];
        for (int i = tid; i < 26 * FST; i += 128) {
            int ly = i / FST, lx = i % FST;
            float vA = 0.f, vB = 0.f;
            if (lx < 74) {
                int off = (y0 + 6 + ly) * HP + (x0 + 6 + lx);
                vA = baseA[off];
                vB = baseB[off];
            }
            sT[i] = pack2(vA, vB);
        }
        if (tid < 121) {
            float2 wA = ck2[fA * 121 + 120 - tid];
            float2 wB = ck2[fB * 121 + 120 - tid];
            sK[tid] = make_ulonglong2(pack2(wA.x, wB.x), pack2(wA.y, wB.y));
        }
        __syncthreads();
#pragma unroll 1
        for (int ky = 0; ky < 11; ky++) {
            u64 v[18];
            const u64* rowp = &sT[(ty + ky) * FST + txg];
#pragma unroll
            for (int q = 0; q < 18; q++) v[q] = rowp[q];
#pragma unroll
            for (int kx = 0; kx < 11; kx++) {
                ulonglong2 wv = sK[ky * 11 + kx];
#pragma unroll
                for (int j = 0; j < 8; j++) {
                    fma2(accre[j], v[kx + j], wv.x);
                    fma2(accim[j], v[kx + j], wv.y);
                }
            }
        }
    }
    int y = y0 + ty;
    float2* dst = &g_adj[((chunk * NB + n) * HH + y) * WW + x0 + txg];
#pragma unroll
    for (int j = 0; j < 8; j++) {
        float a, b, c, d;
        unpack2(accre[j], a, b);
        unpack2(accim[j], c, d);
        dst[j] = make_float2(a + b, c + d);
    }
}

// ------------- final combine: u - Ru - Du ----------------------------------
__global__ void k_combine(const float* __restrict__ u,
                          const float* __restrict__ lamb,
                          float2* __restrict__ out) {
    int idx = blockIdx.x * blockDim.x + threadIdx.x;
    if (idx >= NB * HH * WW) return;
    int pix = idx % (HH * WW), n = idx / (HH * WW);
    float lam = lamb[0];
    float2 ru = make_float2(0.f, 0.f);
#pragma unroll
    for (int c = 0; c < 4; c++) {
        float2 v = g_adj[(c * NB + n) * (HH * WW) + pix];
        ru.x += v.x; ru.y += v.y;
    }
    float2 du = make_float2(0.f, 0.f);
#pragma unroll 1
    for (int c = 0; c < NCOIL; c++) {
        float2 v = g_work[(n * NCOIL + c) * (HH * WW) + pix];
        du.x += v.x; du.y += v.y;
    }
    float2 uu = ((const float2*)u)[idx];
    float2 o;
    o.x = uu.x - ru.x * (1.f / 32.f) - lam * du.x;
    o.y = uu.y - ru.y * (1.f / 32.f) - lam * du.y;
    out[idx] = o;
}

// ---------------------------------------------------------------------------
extern "C" void kernel_launch(void* const* d_in, const int* in_sizes, int n_in,
                              void* d_out, int out_size) {
    const float* u_t   = (const float*)d_in[0];
    const float* fdat  = (const float*)d_in[1];
    const float* cs    = (const float*)d_in[2];
    const float* mask  = (const float*)d_in[3];
    const float* ck    = (const float*)d_in[4];
    const float* w     = (const float*)d_in[5];
    const float* mu    = (const float*)d_in[6];
    const float* sigma = (const float*)d_in[7];
    const float* lamb  = (const float*)d_in[8];
    float2* out = (float2*)d_out;

    cudaFuncSetAttribute(k_conv,
        cudaFuncAttributePreferredSharedMemoryCarveout, 100);

    k_tw<<<1, 320>>>();
    k_lut<<<NF, 256>>>(w, mu, sigma);
    k_pad<<<(NB * HP * HP + 255) / 256, 256>>>(u_t);
    k_conv<<<dim3(6, 11, NB * 16), 256>>>(ck);

    k_fft_row_fwd<<<2400, 320>>>(u_t, cs);
    k_fft_col_mid<<<2400, 320>>>(fdat, mask);
    k_fft_row_inv<<<2400, 320>>>(cs);

    k_adj<<<dim3(5, 20, NB * 4), 128>>>(ck);
    k_combine<<<(NB * HH * WW + 255) / 256, 256>>>(u_t, lamb, out);
}